// round 14
// baseline (speedup 1.0000x reference)
#include <cuda_runtime.h>
#include <cstdint>

// Problem constants (from reference): B=32, S=1024, D=512
#define BB 32
#define SS 1024
#define DD 512
#define DV4 (DD / 4)     // 128 float4 per row
#define TAILW 64         // s-blocks per batch sharing the tail zero-fill
#define PERT (SS / 128)  // durations per scan thread = 8

// Scratch (allocation-free; returned to initial state by the last block)
__device__ int g_ends[BB * SS];       // inclusive cumsum of clamped durations
__device__ int g_totals[BB];          // total_lengths per batch
__device__ int g_flag[BB];            // per-batch "scan done" flag (0 at entry)
__device__ unsigned int g_done;       // finished-block counter (0 at entry)

__device__ __forceinline__ void st_release(int* p, int v) {
    asm volatile("st.global.release.gpu.b32 [%0], %1;" :: "l"(p), "r"(v) : "memory");
}
__device__ __forceinline__ int ld_acquire(int* p) {
    int v;
    asm volatile("ld.global.acquire.gpu.b32 %0, [%1];" : "=r"(v) : "l"(p) : "memory");
    return v;
}

// ---------------------------------------------------------------------------
// Single fused kernel. Grid (SS, BB), 128 threads, 1 source row per block.
//  * Blocks (s<32, b==0) — linear bids 0..31, all wave-1 resident — each
//    compute the duration scan for batch s CONCURRENTLY and publish it.
//    => one scan-latency bubble total, not one per batch (the R10 mistake).
//  * Every block then acquire-waits on its batch flag (wave 1 only; later
//    waves find it set) and streams its row's d copies to the output.
//  * Last finishing block resets flags + counter for the next graph replay
//    (safe: stream ordering serializes replays).
// ---------------------------------------------------------------------------
__global__ void __launch_bounds__(128)
lenreg_kernel(const float4* __restrict__ x4,
              const float*  __restrict__ dur,
              const int*    __restrict__ scale_raw,
              float4* __restrict__ out4, int T,
              float* __restrict__ len_out, int write_len)
{
    const int s   = blockIdx.x;
    const int b   = blockIdx.y;
    const int tid = threadIdx.x;

    // Scan-independent prelude: start this row's x read immediately.
    const float4 v = __ldcs(&x4[((size_t)b * SS + s) * DV4 + tid]);

    if (b == 0 && s < BB) {
        // ---- designated scan block: computes the scan for batch `s` ----
        const int sb = s;   // batch this block scans
        const int   iv = scale_raw[0];
        const float fvs = __int_as_float(iv);
        const float af = fabsf(fvs);
        const float scale = (af >= 1e-6f && af <= 1e6f) ? fvs : (float)iv;

        const float4* db4 = (const float4*)(dur + sb * SS);
        float4 a0 = __ldg(&db4[2 * tid]);
        float4 a1 = __ldg(&db4[2 * tid + 1]);
        int d[PERT];
        d[0] = (int)(a0.x * scale + 0.5f); d[1] = (int)(a0.y * scale + 0.5f);
        d[2] = (int)(a0.z * scale + 0.5f); d[3] = (int)(a0.w * scale + 0.5f);
        d[4] = (int)(a1.x * scale + 0.5f); d[5] = (int)(a1.y * scale + 0.5f);
        d[6] = (int)(a1.z * scale + 0.5f); d[7] = (int)(a1.w * scale + 0.5f);
        int tsum = 0;
        #pragma unroll
        for (int i = 0; i < PERT; ++i) { if (d[i] < 1) d[i] = 1; tsum += d[i]; }

        // inclusive scan of per-thread sums (4 warps)
        const int lane = tid & 31, warp = tid >> 5;
        int w = tsum;
        #pragma unroll
        for (int o = 1; o < 32; o <<= 1) {
            int n = __shfl_up_sync(0xffffffffu, w, o);
            if (lane >= o) w += n;
        }
        __shared__ int wsum[4];
        if (lane == 31) wsum[warp] = w;
        __syncthreads();
        int base = w - tsum, tot = 0;
        #pragma unroll
        for (int k = 0; k < 4; ++k) {
            if (k < warp) base += wsum[k];
            tot += wsum[k];
        }

        int e[PERT];
        e[0] = base + d[0];
        #pragma unroll
        for (int i = 1; i < PERT; ++i) e[i] = e[i - 1] + d[i];
        int4* eb = (int4*)(g_ends + sb * SS);
        eb[2 * tid]     = make_int4(e[0], e[1], e[2], e[3]);
        eb[2 * tid + 1] = make_int4(e[4], e[5], e[6], e[7]);
        if (tid == 127) {
            g_totals[sb] = tot;
            if (write_len) len_out[sb] = (float)tot;
        }
        __threadfence();
        __syncthreads();
        if (tid == 127) st_release(&g_flag[sb], 1);
    }

    // ---- wait until this batch's scan is published (wave 1 only) ----
    if (tid == 0) {
        while (ld_acquire(&g_flag[b]) == 0) __nanosleep(100);
    }
    __syncthreads();

    // ---- scatter-expand this row ----
    const int end   = __ldcg(&g_ends[b * SS + s]);
    const int start = (s > 0) ? __ldcg(&g_ends[b * SS + s - 1]) : 0;

    float4* dst = out4 + ((size_t)b * T + start) * DV4 + tid;
    for (int r = start; r < end; ++r) {
        __stcs(dst, v);
        dst += DV4;
    }

    // ---- fused tail zero-fill: rows [tot, T) shared by last TAILW s-blocks
    if (s >= SS - TAILW) {
        const int tot = __ldcg(&g_totals[b]);
        const float4 z = make_float4(0.f, 0.f, 0.f, 0.f);
        for (int r = tot + (s - (SS - TAILW)); r < T; r += TAILW) {
            __stcs(out4 + ((size_t)b * T + r) * DV4 + tid, z);
        }
    }

    // ---- last block resets sync state for the next graph replay ----
    __syncthreads();
    if (tid == 0) {
        __threadfence();
        unsigned int prev = atomicAdd(&g_done, 1u);
        if (prev == (unsigned)(SS * BB - 1)) {
            #pragma unroll
            for (int i = 0; i < BB; ++i) g_flag[i] = 0;
            g_done = 0;
            __threadfence();
        }
    }
}

// ---------------------------------------------------------------------------
extern "C" void kernel_launch(void* const* d_in, const int* in_sizes, int n_in,
                              void* d_out, int out_size)
{
    const float4* x4    = (const float4*)d_in[0];   // x: (B,S,D) float32
    const float*  dur   = (const float*)d_in[1];    // durations: (B,S) float32
    const int*    scale = (const int*)d_in[2];      // duration_scale: scalar
    float* out = (float*)d_out;

    // Recover T (max total length) from out_size:
    //   out only:           out_size = B*T*D
    //   out + lengths tail: out_size = B*T*D + B
    int T, has_len;
    if (out_size % (BB * DD) == 0) {
        T = out_size / (BB * DD);
        has_len = 0;
    } else {
        T = (out_size - BB) / (BB * DD);
        has_len = 1;
    }

    lenreg_kernel<<<dim3(SS, BB), 128>>>(x4, dur, scale, (float4*)out, T,
                                         out + (size_t)BB * T * DD, has_len);
}

// round 15
// speedup vs baseline: 1.1146x; 1.1146x over previous
#include <cuda_runtime.h>
#include <cstdint>

// Problem constants (from reference): B=32, S=1024, D=512
#define BB 32
#define SS 1024
#define DD 512
#define DV4 (DD / 4)     // 128 float4 per row
#define TAILW 64         // s-blocks per batch sharing the tail zero-fill
#define PERT (SS / 128)  // durations per scan thread = 8

// Scratch (allocation-free per harness rules)
__device__ int g_ends[BB * SS];   // inclusive cumsum of clamped durations, per batch
__device__ int g_totals[BB];      // total_lengths per batch

// ---------------------------------------------------------------------------
// Kernel A: per-batch duration round/clamp + inclusive scan.
// One block per batch, 128 threads, 8 durations/thread (2x float4).
// Shortest-latency variant: single __syncthreads, 4 warp partials.
// ---------------------------------------------------------------------------
__global__ void __launch_bounds__(128)
durscan_kernel(const float* __restrict__ durations, const int* __restrict__ scale_raw,
               float* __restrict__ len_out, int write_len)
{
    const int b   = blockIdx.x;
    const int tid = threadIdx.x;
    const int lane = tid & 31;
    const int warp = tid >> 5;

    // duration_scale dtype is ambiguous (python int 1 vs float 1.0).
    // Interpret the raw word as float if in a sane range, else as int.
    const int   iv = scale_raw[0];
    const float fvs = __int_as_float(iv);
    const float af = fabsf(fvs);
    const float scale = (af >= 1e-6f && af <= 1e6f) ? fvs : (float)iv;

    const float4* db4 = (const float4*)(durations + b * SS);
    const float4 a0 = __ldg(&db4[2 * tid]);
    const float4 a1 = __ldg(&db4[2 * tid + 1]);
    int d[PERT];
    d[0] = (int)(a0.x * scale + 0.5f); d[1] = (int)(a0.y * scale + 0.5f);
    d[2] = (int)(a0.z * scale + 0.5f); d[3] = (int)(a0.w * scale + 0.5f);
    d[4] = (int)(a1.x * scale + 0.5f); d[5] = (int)(a1.y * scale + 0.5f);
    d[6] = (int)(a1.z * scale + 0.5f); d[7] = (int)(a1.w * scale + 0.5f);
    int tsum = 0;
    #pragma unroll
    for (int i = 0; i < PERT; ++i) { if (d[i] < 1) d[i] = 1; tsum += d[i]; }

    // Inclusive scan of per-thread sums: warp shuffle + 4 warp partials.
    int w = tsum;
    #pragma unroll
    for (int o = 1; o < 32; o <<= 1) {
        int n = __shfl_up_sync(0xffffffffu, w, o);
        if (lane >= o) w += n;
    }
    __shared__ int wsum[4];
    if (lane == 31) wsum[warp] = w;
    __syncthreads();
    int base = w - tsum, tot = 0;
    #pragma unroll
    for (int k = 0; k < 4; ++k) {
        if (k < warp) base += wsum[k];
        tot += wsum[k];
    }

    int e[PERT];
    e[0] = base + d[0];
    #pragma unroll
    for (int i = 1; i < PERT; ++i) e[i] = e[i - 1] + d[i];
    int4* eb = (int4*)(g_ends + b * SS);
    eb[2 * tid]     = make_int4(e[0], e[1], e[2], e[3]);
    eb[2 * tid + 1] = make_int4(e[4], e[5], e[6], e[7]);

    if (tid == 127) {
        g_totals[b] = tot;
        if (write_len) len_out[b] = (float)tot;
    }
}

// ---------------------------------------------------------------------------
// Kernel B: scatter-expand + fused tail zero-fill. (Best measured: 46.85us)
// One 128-thread block per (s, b) source row. Each thread holds one float4 of
// x[b][s] in a register and streams it to output rows [start, end).
// The last TAILW s-blocks of each batch additionally zero-fill the masked
// tail rows [tot, T) in a strided, balanced fashion (output is 0xAA-poisoned).
// ---------------------------------------------------------------------------
__global__ void __launch_bounds__(128)
scatter_kernel(const float4* __restrict__ x4, float4* __restrict__ out4, int T)
{
    const int s = blockIdx.x;
    const int b = blockIdx.y;

    const int end   = g_ends[b * SS + s];
    const int start = (s > 0) ? g_ends[b * SS + s - 1] : 0;

    const float4 v = __ldcs(&x4[((size_t)b * SS + s) * DV4 + threadIdx.x]);

    float4* dst = out4 + ((size_t)b * T + start) * DV4 + threadIdx.x;
    for (int r = start; r < end; ++r) {
        __stcs(dst, v);
        dst += DV4;
    }

    // Fused tail zero-fill: rows [tot, T) shared across the last TAILW blocks.
    if (s >= SS - TAILW) {
        const int tot = g_totals[b];
        const float4 z = make_float4(0.f, 0.f, 0.f, 0.f);
        for (int r = tot + (s - (SS - TAILW)); r < T; r += TAILW) {
            __stcs(out4 + ((size_t)b * T + r) * DV4 + threadIdx.x, z);
        }
    }
}

// ---------------------------------------------------------------------------
extern "C" void kernel_launch(void* const* d_in, const int* in_sizes, int n_in,
                              void* d_out, int out_size)
{
    const float4* x4    = (const float4*)d_in[0];   // x: (B,S,D) float32
    const float*  dur   = (const float*)d_in[1];    // durations: (B,S) float32
    const int*    scale = (const int*)d_in[2];      // duration_scale: scalar
    float* out = (float*)d_out;

    // Recover T (max total length) from out_size:
    //   out only:           out_size = B*T*D
    //   out + lengths tail: out_size = B*T*D + B
    int T, has_len;
    if (out_size % (BB * DD) == 0) {
        T = out_size / (BB * DD);
        has_len = 0;
    } else {
        T = (out_size - BB) / (BB * DD);
        has_len = 1;
    }

    durscan_kernel<<<BB, 128>>>(dur, scale, out + (size_t)BB * T * DD, has_len);
    scatter_kernel<<<dim3(SS, BB), 128>>>(x4, (float4*)out, T);
}

// round 16
// speedup vs baseline: 1.1152x; 1.0006x over previous
#include <cuda_runtime.h>
#include <cstdint>

// Problem constants (from reference): B=32, S=1024, D=512
#define BB 32
#define SS 1024
#define DD 512
#define DV4 (DD / 4)     // 128 float4 per row
#define TAILW 64         // s-blocks per batch sharing the tail zero-fill
#define PERT (SS / 128)  // durations per scan thread = 8

// Scratch (allocation-free per harness rules)
__device__ int2 g_se[BB * SS];    // (start, end) per source row
__device__ int  g_totals[BB];     // total_lengths per batch

// ---------------------------------------------------------------------------
// Kernel A: per-batch duration round/clamp + inclusive scan -> (start,end).
// One block per batch, 128 threads, 8 durations/thread (2x float4).
// Triggers programmatic launch completion immediately so the scatter kernel's
// prelude (block launch + x row loads) overlaps this kernel's execution.
// ---------------------------------------------------------------------------
__global__ void __launch_bounds__(128)
durscan_kernel(const float* __restrict__ durations, const int* __restrict__ scale_raw,
               float* __restrict__ len_out, int write_len)
{
    cudaTriggerProgrammaticLaunchCompletion();

    const int b   = blockIdx.x;
    const int tid = threadIdx.x;
    const int lane = tid & 31;
    const int warp = tid >> 5;

    // duration_scale dtype is ambiguous (python int 1 vs float 1.0).
    // Interpret the raw word as float if in a sane range, else as int.
    const int   iv = scale_raw[0];
    const float fvs = __int_as_float(iv);
    const float af = fabsf(fvs);
    const float scale = (af >= 1e-6f && af <= 1e6f) ? fvs : (float)iv;

    const float4* db4 = (const float4*)(durations + b * SS);
    const float4 a0 = __ldg(&db4[2 * tid]);
    const float4 a1 = __ldg(&db4[2 * tid + 1]);
    int d[PERT];
    d[0] = (int)(a0.x * scale + 0.5f); d[1] = (int)(a0.y * scale + 0.5f);
    d[2] = (int)(a0.z * scale + 0.5f); d[3] = (int)(a0.w * scale + 0.5f);
    d[4] = (int)(a1.x * scale + 0.5f); d[5] = (int)(a1.y * scale + 0.5f);
    d[6] = (int)(a1.z * scale + 0.5f); d[7] = (int)(a1.w * scale + 0.5f);
    int tsum = 0;
    #pragma unroll
    for (int i = 0; i < PERT; ++i) { if (d[i] < 1) d[i] = 1; tsum += d[i]; }

    // Inclusive scan of per-thread sums: warp shuffle + 4 warp partials.
    int w = tsum;
    #pragma unroll
    for (int o = 1; o < 32; o <<= 1) {
        int n = __shfl_up_sync(0xffffffffu, w, o);
        if (lane >= o) w += n;
    }
    __shared__ int wsum[4];
    if (lane == 31) wsum[warp] = w;
    __syncthreads();
    int base = w - tsum, tot = 0;
    #pragma unroll
    for (int k = 0; k < 4; ++k) {
        if (k < warp) base += wsum[k];
        tot += wsum[k];
    }

    // Emit (start, end) pairs: one 8B word per source row.
    int e = base;
    int4* sb = (int4*)(g_se + (size_t)b * SS + tid * PERT);
    int4 p01, p23, p45, p67;
    p01.x = e;        p01.y = e + d[0]; e = p01.y;
    p01.z = e;        p01.w = e + d[1]; e = p01.w;
    p23.x = e;        p23.y = e + d[2]; e = p23.y;
    p23.z = e;        p23.w = e + d[3]; e = p23.w;
    p45.x = e;        p45.y = e + d[4]; e = p45.y;
    p45.z = e;        p45.w = e + d[5]; e = p45.w;
    p67.x = e;        p67.y = e + d[6]; e = p67.y;
    p67.z = e;        p67.w = e + d[7]; e = p67.w;
    sb[0] = p01; sb[1] = p23; sb[2] = p45; sb[3] = p67;

    if (tid == 127) {
        g_totals[b] = tot;
        if (write_len) len_out[b] = (float)tot;
    }
}

// ---------------------------------------------------------------------------
// Kernel B: scatter-expand + fused tail zero-fill (PDL secondary).
// One 128-thread block per (s, b) source row. The x-row load (independent of
// the scan) issues BEFORE the grid dependency sync; the (start,end) pair load
// comes after. Store/tail loops identical to the measured 46.8us version.
// ---------------------------------------------------------------------------
__global__ void __launch_bounds__(128)
scatter_kernel(const float4* __restrict__ x4, float4* __restrict__ out4, int T)
{
    const int s = blockIdx.x;
    const int b = blockIdx.y;

    // Scan-independent prelude: start this row's x read immediately.
    const float4 v = __ldcs(&x4[((size_t)b * SS + s) * DV4 + threadIdx.x]);

    cudaGridDependencySynchronize();

    const int2 se = *(const int2*)&g_se[(size_t)b * SS + s];
    const int start = se.x;
    const int end   = se.y;

    float4* dst = out4 + ((size_t)b * T + start) * DV4 + threadIdx.x;
    for (int r = start; r < end; ++r) {
        __stcs(dst, v);
        dst += DV4;
    }

    // Fused tail zero-fill: rows [tot, T) shared across the last TAILW blocks.
    if (s >= SS - TAILW) {
        const int tot = g_totals[b];
        const float4 z = make_float4(0.f, 0.f, 0.f, 0.f);
        for (int r = tot + (s - (SS - TAILW)); r < T; r += TAILW) {
            __stcs(out4 + ((size_t)b * T + r) * DV4 + threadIdx.x, z);
        }
    }
}

// ---------------------------------------------------------------------------
extern "C" void kernel_launch(void* const* d_in, const int* in_sizes, int n_in,
                              void* d_out, int out_size)
{
    const float4* x4    = (const float4*)d_in[0];   // x: (B,S,D) float32
    const float*  dur   = (const float*)d_in[1];    // durations: (B,S) float32
    const int*    scale = (const int*)d_in[2];      // duration_scale: scalar
    float* out = (float*)d_out;

    // Recover T (max total length) from out_size:
    //   out only:           out_size = B*T*D
    //   out + lengths tail: out_size = B*T*D + B
    int T, has_len;
    if (out_size % (BB * DD) == 0) {
        T = out_size / (BB * DD);
        has_len = 0;
    } else {
        T = (out_size - BB) / (BB * DD);
        has_len = 1;
    }

    durscan_kernel<<<BB, 128>>>(dur, scale, out + (size_t)BB * T * DD, has_len);

    // Scatter as a programmatic dependent launch: its prelude (block ramp +
    // x-row loads) overlaps durscan's execution.
    cudaLaunchConfig_t cfg = {};
    cfg.gridDim  = dim3(SS, BB);
    cfg.blockDim = dim3(128);
    cfg.stream   = 0;
    cudaLaunchAttribute attr;
    attr.id = cudaLaunchAttributeProgrammaticStreamSerialization;
    attr.val.programmaticStreamSerializationAllowed = 1;
    cfg.attrs    = &attr;
    cfg.numAttrs = 1;
    float4* o4 = (float4*)out;
    cudaLaunchKernelEx(&cfg, scatter_kernel, x4, o4, T);
}